// round 2
// baseline (speedup 1.0000x reference)
#include <cuda_runtime.h>
#include <cuda_bf16.h>
#include <math.h>

#define N_PTS 250000
#define N_DET 64
#define NUM_MAGS 10
#define NUM_ROT 10
#define NUM_TRIALS 4
#define NBLK 512
#define CH 489   // ceil(N_PTS / NBLK)

// -------------------- device scratch (no allocation allowed) --------------------
__device__ float g_plane[NUM_TRIALS][8]; // nrm(3), p0(3), nn, den
__device__ int   g_cnt[N_DET * 16];      // per det: [0]=msum, [1..10]=dns bins, [11..14]=inl
__device__ float g_det[N_DET][64];       // packed per-det geometry:
// 0 K(9), 9 CRinv(9), 18 ERinv(9), 27 CT(3), 30 ET(3), 33 PR(9), 42 PT(3),
// 45 cdir(3), 54 size(3), 57 box(4), 61 area_d
__device__ float g_mnmx[6 * N_DET];      // SoA: [mnx|mny|mnz|mxx|mxy|mxz][d]

__constant__ float c_tmpl[8][3] = {
    { 0.5f,  0.5f, -0.5f}, { 0.5f, -0.5f, -0.5f}, {-0.5f, -0.5f, -0.5f}, {-0.5f,  0.5f, -0.5f},
    { 0.5f,  0.5f,  0.5f}, { 0.5f, -0.5f,  0.5f}, {-0.5f, -0.5f,  0.5f}, {-0.5f,  0.5f,  0.5f}};

__device__ __forceinline__ void inv3(const float* a, float* o) {
    float det = a[0]*(a[4]*a[8]-a[5]*a[7]) - a[1]*(a[3]*a[8]-a[5]*a[6]) + a[2]*(a[3]*a[7]-a[4]*a[6]);
    float id = 1.0f / det;
    o[0]=(a[4]*a[8]-a[5]*a[7])*id; o[1]=(a[2]*a[7]-a[1]*a[8])*id; o[2]=(a[1]*a[5]-a[2]*a[4])*id;
    o[3]=(a[5]*a[6]-a[3]*a[8])*id; o[4]=(a[0]*a[8]-a[2]*a[6])*id; o[5]=(a[2]*a[3]-a[0]*a[5])*id;
    o[6]=(a[3]*a[7]-a[4]*a[6])*id; o[7]=(a[1]*a[6]-a[0]*a[7])*id; o[8]=(a[0]*a[4]-a[1]*a[3])*id;
}

__device__ __forceinline__ void mv3(const float* M, const float* v, float* o) {
    o[0] = M[0]*v[0] + M[1]*v[1] + M[2]*v[2];
    o[1] = M[3]*v[0] + M[4]*v[1] + M[5]*v[2];
    o[2] = M[6]*v[0] + M[7]*v[1] + M[8]*v[2];
}

// ==================== K1: setup (planes + counters-zero + per-det geometry) ====================
__global__ void k_setup(const float* __restrict__ points,
                        const float* __restrict__ intr, const float* __restrict__ c2l,
                        const float* __restrict__ iaug, const float* __restrict__ laug,
                        const float* __restrict__ dbox, const float* __restrict__ anchors,
                        const int* __restrict__ labels, const int* __restrict__ camidx) {
    int t = threadIdx.x;
    if (blockIdx.x == 1) {
        // RANSAC planes + zero the global counters
        for (int j = t; j < N_DET * 16; j += blockDim.x) g_cnt[j] = 0;
        if (t < NUM_TRIALS) {
            const int step = N_PTS / 3;  // 83333
            float p0[3], p1[3], p2[3];
            #pragma unroll
            for (int c = 0; c < 3; c++) {
                p0[c] = points[(t)            * 4 + 1 + c];
                p1[c] = points[(t + step)     * 4 + 1 + c];
                p2[c] = points[(t + 2 * step) * 4 + 1 + c];
            }
            float e1[3] = {p1[0]-p0[0], p1[1]-p0[1], p1[2]-p0[2]};
            float e2[3] = {p2[0]-p0[0], p2[1]-p0[1], p2[2]-p0[2]};
            float nx = e1[1]*e2[2] - e1[2]*e2[1];
            float ny = e1[2]*e2[0] - e1[0]*e2[2];
            float nz = e1[0]*e2[1] - e1[1]*e2[0];
            float ss = nx*nx + ny*ny + nz*nz;
            g_plane[t][0] = nx; g_plane[t][1] = ny; g_plane[t][2] = nz;
            g_plane[t][3] = p0[0]; g_plane[t][4] = p0[1]; g_plane[t][5] = p0[2];
            g_plane[t][6] = sqrtf(ss);       // |n|
            g_plane[t][7] = ss + 1e-8f;      // n.n + eps
        }
        return;
    }
    // block 0: per-detection geometry
    int d = t;
    if (d >= N_DET) return;
    int cam = camidx[d];

    float K[9], CR[9], PR[9], ER[9], CT[3], PT[3], ET[3];
    #pragma unroll
    for (int i = 0; i < 3; i++) {
        #pragma unroll
        for (int j = 0; j < 3; j++) {
            K [i*3+j] = intr[cam*16 + i*4 + j];
            CR[i*3+j] = c2l [cam*16 + i*4 + j];
            PR[i*3+j] = iaug[cam*16 + i*4 + j];
            ER[i*3+j] = laug[i*4 + j];
        }
        CT[i] = c2l [cam*16 + i*4 + 3];
        PT[i] = iaug[cam*16 + i*4 + 3];
        ET[i] = laug[i*4 + 3];
    }
    float Kinv[9], CRinv[9], PRinv[9], ERinv[9];
    inv3(K, Kinv); inv3(CR, CRinv); inv3(PR, PRinv); inv3(ER, ERinv);

    float x1 = dbox[d*4+0], y1 = dbox[d*4+1], x2 = dbox[d*4+2], y2 = dbox[d*4+3];
    float lo[3] = {x1, y1, 2.0f}, hi[3] = {x2, y2, 60.0f};
    float whl[3] = {hi[0]-lo[0], hi[1]-lo[1], hi[2]-lo[2]};
    float ctr[3] = {(hi[0]+lo[0])*0.5f, (hi[1]+lo[1])*0.5f, (hi[2]+lo[2])*0.5f};

    float sum[3] = {0,0,0};
    float mn[3] = {1e30f, 1e30f, 1e30f}, mx[3] = {-1e30f, -1e30f, -1e30f};
    #pragma unroll
    for (int k = 0; k < 8; k++) {
        float ci[3], t0[3], t1[3], t2[3];
        #pragma unroll
        for (int c = 0; c < 3; c++) ci[c] = whl[c]*c_tmpl[k][c] + ctr[c] - PT[c];
        mv3(PRinv, ci, t0);
        t0[0] = t0[0]*t0[2]; t0[1] = t0[1]*t0[2];
        mv3(Kinv, t0, t1);
        mv3(CR, t1, t2);
        #pragma unroll
        for (int c = 0; c < 3; c++) t2[c] += CT[c];
        mv3(ER, t2, t0);
        #pragma unroll
        for (int c = 0; c < 3; c++) t0[c] += ET[c];
        float nrm = sqrtf(t0[0]*t0[0] + t0[1]*t0[1] + t0[2]*t0[2]);
        #pragma unroll
        for (int c = 0; c < 3; c++) {
            float dr = t0[c] / (nrm + 1e-8f);
            sum[c] += dr;
            mn[c] = fminf(mn[c], dr);
            mx[c] = fmaxf(mx[c], dr);
        }
    }
    float cd[3] = {sum[0]/8.0f, sum[1]/8.0f, sum[2]/8.0f};
    float cn = sqrtf(cd[0]*cd[0] + cd[1]*cd[1] + cd[2]*cd[2]);
    #pragma unroll
    for (int c = 0; c < 3; c++) cd[c] = cd[c] / (cn + 1e-8f);

    float* G = g_det[d];
    for (int j = 0; j < 9; j++) { G[j] = K[j]; G[9+j] = CRinv[j]; G[18+j] = ERinv[j]; G[33+j] = PR[j]; }
    #pragma unroll
    for (int c = 0; c < 3; c++) {
        G[27+c] = CT[c]; G[30+c] = ET[c]; G[42+c] = PT[c];
        G[45+c] = cd[c];
        G[54+c] = anchors[labels[d]*3 + c];
        g_mnmx[c*N_DET + d]       = mn[c];
        g_mnmx[(3 + c)*N_DET + d] = mx[c];
    }
    G[57] = x1; G[58] = y1; G[59] = x2; G[60] = y2;
    G[61] = (x2 - x1) * (y2 - y1);
}

// ==================== K2: fused per-point prep + (det,point) accumulation ====================
__global__ void __launch_bounds__(256) k_main(const float* __restrict__ points) {
    __shared__ float4   s_p[CH];
    __shared__ uint4    s_f[CH];
    __shared__ unsigned s_acc[256][6];   // 5 used + pad (bank-conflict-free)

    int start = blockIdx.x * CH;

    // ---- phase 1: prep this block's chunk into shared ----
    for (int j = threadIdx.x; j < CH; j += 256) {
        int i = start + j;
        float px = 2.0e9f, py = 0.0f, pz = 0.0f;
        unsigned nb0 = 0, nb1 = 0, nb2 = 0, ib = 0;
        if (i < N_PTS) {
            float4 pt = ((const float4*)points)[i];
            float x = pt.y, y = pt.z, z = pt.w;
            float pmag = sqrtf(x*x + y*y + z*z);
            float den = pmag + 1e-8f;
            py = y / den; pz = z / den;
            bool rok = (pmag >= 2.0f) && (pmag <= 60.0f);
            px = rok ? (x / den) : 2.0e9f;   // sentinel: direction test always fails

            #pragma unroll
            for (int m = 0; m < NUM_MAGS; m++) {
                float mg = 2.0f + (float)m * (58.0f / 9.0f);
                unsigned b = (fabsf(pmag - mg) < 5.8f) ? 1u : 0u;
                if (m < 4)      nb0 |= b << (8 * m);
                else if (m < 8) nb1 |= b << (8 * (m - 4));
                else            nb2 |= b << (8 * (m - 8));
            }
            #pragma unroll
            for (int t = 0; t < NUM_TRIALS; t++) {
                float nx = g_plane[t][0], ny = g_plane[t][1], nz = g_plane[t][2];
                float dot = nx*(x - g_plane[t][3]) + ny*(y - g_plane[t][4]) + nz*(z - g_plane[t][5]);
                float tt = dot / g_plane[t][7];
                float dist = fabsf(tt) * g_plane[t][6];
                ib |= ((dist < 0.69f) ? 1u : 0u) << (8 * t);
            }
        }
        s_p[j] = make_float4(px, py, pz, 0.0f);
        s_f[j] = make_uint4(nb0, nb1, nb2, ib);
    }
    __syncthreads();

    // ---- phase 2: lane = det, 4 point-subgroups ----
    int d = threadIdx.x & 63;
    int g = threadIdx.x >> 6;
    float mnx = g_mnmx[0*N_DET + d], mny = g_mnmx[1*N_DET + d], mnz = g_mnmx[2*N_DET + d];
    float mxx = g_mnmx[3*N_DET + d], mxy = g_mnmx[4*N_DET + d], mxz = g_mnmx[5*N_DET + d];

    unsigned msum = 0, a0 = 0, a1 = 0, a2 = 0, ai = 0;
    #pragma unroll 2
    for (int j = g; j < CH; j += 4) {
        float4 p = s_p[j];
        uint4  f = s_f[j];
        bool mk = (p.x >= mnx) & (p.x <= mxx) & (p.y >= mny) & (p.y <= mxy)
                & (p.z >= mnz) & (p.z <= mxz);
        if (mk) {
            msum += 1u;
            a0 += f.x; a1 += f.y; a2 += f.z; ai += f.w;
        }
    }
    s_acc[threadIdx.x][0] = msum;
    s_acc[threadIdx.x][1] = a0;
    s_acc[threadIdx.x][2] = a1;
    s_acc[threadIdx.x][3] = a2;
    s_acc[threadIdx.x][4] = ai;
    __syncthreads();

    // ---- phase 3: 64 threads reduce 4 subgroups, unpack bytes, atomically add globally ----
    if (threadIdx.x < N_DET) {
        int c[15];
        #pragma unroll
        for (int s = 0; s < 15; s++) c[s] = 0;
        #pragma unroll
        for (int r = 0; r < 4; r++) {
            const unsigned* w = s_acc[threadIdx.x + 64 * r];
            c[0] += (int)w[0];
            unsigned w1 = w[1], w2 = w[2], w3 = w[3], w4 = w[4];
            #pragma unroll
            for (int b = 0; b < 4; b++) c[1 + b]  += (int)((w1 >> (8*b)) & 255u);
            #pragma unroll
            for (int b = 0; b < 4; b++) c[5 + b]  += (int)((w2 >> (8*b)) & 255u);
            #pragma unroll
            for (int b = 0; b < 2; b++) c[9 + b]  += (int)((w3 >> (8*b)) & 255u);
            #pragma unroll
            for (int b = 0; b < 4; b++) c[11 + b] += (int)((w4 >> (8*b)) & 255u);
        }
        #pragma unroll
        for (int s = 0; s < 15; s++) atomicAdd(&g_cnt[threadIdx.x * 16 + s], c[s]);
    }
}

// ==================== K3: inline IoU + scoring + argmax + output ====================
__global__ void k_final(const float* __restrict__ det_scores, float* __restrict__ out) {
    int d = blockIdx.x;
    int t = threadIdx.x;
    __shared__ float sdns[NUM_MAGS];
    __shared__ float spln;
    __shared__ float ssc[128];

    const float* G = g_det[d];

    if (t < NUM_MAGS) sdns[t] = (float)g_cnt[d*16 + 1 + t];
    __syncthreads();
    if (t == 0) {
        float mxv = sdns[0];
        for (int m = 1; m < NUM_MAGS; m++) mxv = fmaxf(mxv, sdns[m]);
        for (int m = 0; m < NUM_MAGS; m++) sdns[m] = sdns[m] / (mxv + 1e-6f);
        float msum = (float)g_cnt[d*16];
        float pln = -1e30f;
        for (int tt = 0; tt < NUM_TRIALS; tt++)
            pln = fmaxf(pln, ((float)g_cnt[d*16 + 11 + tt]) / (msum + 1e-6f));
        spln = pln;
    }

    float iou = 0.0f;
    if (t < 100) {
        float K[9], CRinv[9], ERinv[9], PR[9], CT[3], ET[3], PT[3], cd[3], sz[3];
        for (int j = 0; j < 9; j++) { K[j]=G[j]; CRinv[j]=G[9+j]; ERinv[j]=G[18+j]; PR[j]=G[33+j]; }
        #pragma unroll
        for (int c = 0; c < 3; c++) { CT[c]=G[27+c]; ET[c]=G[30+c]; PT[c]=G[42+c]; cd[c]=G[45+c]; sz[c]=G[54+c]; }
        float x1 = G[57], y1 = G[58], x2 = G[59], y2 = G[60], area_d = G[61];

        int m = t / 10, r = t % 10;
        float mag = 2.0f + (float)m * (58.0f / 9.0f);
        float ry  = (float)r * (3.14159265358979f / 9.0f);
        float cs = cosf(ry), sn = sinf(ry);
        float cen[3] = {cd[0]*mag, cd[1]*mag, cd[2]*mag};

        float umin = 1e30f, umax = -1e30f, vmin = 1e30f, vmax = -1e30f;
        #pragma unroll
        for (int k = 0; k < 8; k++) {
            float bx = sz[0]*c_tmpl[k][0], by = sz[1]*c_tmpl[k][1], bz = sz[2]*c_tmpl[k][2];
            float c3[3] = {cen[0] + bx*cs - by*sn, cen[1] + bx*sn + by*cs, cen[2] + bz};
            float t0[3], t1[3], t2[3];
            #pragma unroll
            for (int c = 0; c < 3; c++) t0[c] = c3[c] - ET[c];
            mv3(ERinv, t0, t1);
            #pragma unroll
            for (int c = 0; c < 3; c++) t1[c] -= CT[c];
            mv3(CRinv, t1, t2);
            mv3(K, t2, t0);
            float depth = fmaxf(t0[2], 0.001f);
            float qq[3] = {t0[0]/depth, t0[1]/depth, depth};
            mv3(PR, qq, t1);
            #pragma unroll
            for (int c = 0; c < 3; c++) t1[c] += PT[c];
            float u = fminf(fmaxf(t1[0], 0.0f), 1600.0f);
            float v = fminf(fmaxf(t1[1], 0.0f), 900.0f);
            umin = fminf(umin, u); umax = fmaxf(umax, u);
            vmin = fminf(vmin, v); vmax = fmaxf(vmax, v);
        }
        float ix1 = fmaxf(umin, x1), iy1 = fmaxf(vmin, y1);
        float ix2 = fminf(umax, x2), iy2 = fminf(vmax, y2);
        float inter = fmaxf(ix2 - ix1, 0.0f) * fmaxf(iy2 - iy1, 0.0f);
        float area_p = (umax - umin) * (vmax - vmin);
        iou = inter / (area_p + area_d - inter + 1e-6f);
    }
    __syncthreads();   // sdns/spln ready
    if (t < 100) {
        int m = t / 10;
        const float IOU_W = 0.91f, IOU_W1 = (float)(1.0 - 0.91);
        const float PLN_W = 0.92f, PLN_W1 = (float)(1.0 - 0.92);
        float base = IOU_W * iou + IOU_W1 * sdns[m];
        ssc[t] = PLN_W * base + PLN_W1 * spln;
    } else {
        ssc[t] = -1e30f;
    }
    __syncthreads();
    if (t == 0) {
        int best = 0; float bs = ssc[0];
        for (int i = 1; i < 100; i++) if (ssc[i] > bs) { bs = ssc[i]; best = i; }
        int m = best / 10, r = best % 10;
        float mag = 2.0f + (float)m * (58.0f / 9.0f);
        float* o = out + d*8;
        o[0] = G[45] * mag;
        o[1] = G[46] * mag;
        o[2] = G[47] * mag;
        o[3] = G[54]; o[4] = G[55]; o[5] = G[56];
        o[6] = (float)r * (3.14159265358979f / 9.0f);
        o[7] = bs * det_scores[d];
    }
}

// -------------------- launch --------------------
extern "C" void kernel_launch(void* const* d_in, const int* in_sizes, int n_in,
                              void* d_out, int out_size) {
    const float* points  = (const float*)d_in[0];
    const float* intr    = (const float*)d_in[1];
    const float* c2l     = (const float*)d_in[2];
    const float* iaug    = (const float*)d_in[3];
    const float* laug    = (const float*)d_in[4];
    const float* dbox    = (const float*)d_in[5];
    const float* dscores = (const float*)d_in[6];
    const float* anchors = (const float*)d_in[7];
    const int*   labels  = (const int*)d_in[8];
    const int*   camidx  = (const int*)d_in[9];
    float* out = (float*)d_out;

    k_setup<<<2, 128>>>(points, intr, c2l, iaug, laug, dbox, anchors, labels, camidx);
    k_main<<<NBLK, 256>>>(points);
    k_final<<<N_DET, 128>>>(dscores, out);
}

// round 7
// speedup vs baseline: 1.1004x; 1.1004x over previous
#include <cuda_runtime.h>
#include <cuda_bf16.h>
#include <math.h>

#define N_PTS 250000
#define N_DET 64
#define NUM_MAGS 10
#define NUM_ROT 10
#define NUM_TRIALS 4
#define NBLK 512
#define CH 489   // ceil(N_PTS / NBLK)

// -------------------- device scratch (no allocation allowed) --------------------
__device__ int   g_cnt[N_DET * 16];      // zero at load; k_final re-zeroes after use
__device__ float g_det[N_DET][64];       // packed per-det geometry (written by k_main block 0):
// 0 K(9), 9 CRinv(9), 18 ERinv(9), 27 CT(3), 30 ET(3), 33 PR(9), 42 PT(3),
// 45 cdir(3), 54 size(3), 57 box(4), 61 area_d

__constant__ float c_tmpl[8][3] = {
    { 0.5f,  0.5f, -0.5f}, { 0.5f, -0.5f, -0.5f}, {-0.5f, -0.5f, -0.5f}, {-0.5f,  0.5f, -0.5f},
    { 0.5f,  0.5f,  0.5f}, { 0.5f, -0.5f,  0.5f}, {-0.5f, -0.5f,  0.5f}, {-0.5f,  0.5f,  0.5f}};

__device__ __forceinline__ void inv3(const float* a, float* o) {
    float det = a[0]*(a[4]*a[8]-a[5]*a[7]) - a[1]*(a[3]*a[8]-a[5]*a[6]) + a[2]*(a[3]*a[7]-a[4]*a[6]);
    float id = 1.0f / det;
    o[0]=(a[4]*a[8]-a[5]*a[7])*id; o[1]=(a[2]*a[7]-a[1]*a[8])*id; o[2]=(a[1]*a[5]-a[2]*a[4])*id;
    o[3]=(a[5]*a[6]-a[3]*a[8])*id; o[4]=(a[0]*a[8]-a[2]*a[6])*id; o[5]=(a[2]*a[3]-a[0]*a[5])*id;
    o[6]=(a[3]*a[7]-a[4]*a[6])*id; o[7]=(a[1]*a[6]-a[0]*a[7])*id; o[8]=(a[0]*a[4]-a[1]*a[3])*id;
}

__device__ __forceinline__ void mv3(const float* M, const float* v, float* o) {
    o[0] = M[0]*v[0] + M[1]*v[1] + M[2]*v[2];
    o[1] = M[3]*v[0] + M[4]*v[1] + M[5]*v[2];
    o[2] = M[6]*v[0] + M[7]*v[1] + M[8]*v[2];
}

// ==================== K1: fused setup + prep + (det,point) accumulation ====================
__global__ void __launch_bounds__(256) k_main(
        const float* __restrict__ points,
        const float* __restrict__ intr, const float* __restrict__ c2l,
        const float* __restrict__ iaug, const float* __restrict__ laug,
        const float* __restrict__ dbox, const float* __restrict__ anchors,
        const int* __restrict__ labels, const int* __restrict__ camidx) {
    __shared__ float    s_plane[NUM_TRIALS][8];
    __shared__ float    s_mnmx[6][N_DET];
    __shared__ float4   s_p[CH];
    __shared__ uint4    s_f[CH];
    __shared__ unsigned s_acc[256][6];   // 5 used + pad

    const int tid = threadIdx.x;
    const int start = blockIdx.x * CH;

    // ---- step A: RANSAC planes (threads 0-3) ----
    if (tid < NUM_TRIALS) {
        const int step = N_PTS / 3;  // 83333
        float p0[3], p1[3], p2[3];
        #pragma unroll
        for (int c = 0; c < 3; c++) {
            p0[c] = points[(tid)            * 4 + 1 + c];
            p1[c] = points[(tid + step)     * 4 + 1 + c];
            p2[c] = points[(tid + 2 * step) * 4 + 1 + c];
        }
        float e1[3] = {p1[0]-p0[0], p1[1]-p0[1], p1[2]-p0[2]};
        float e2[3] = {p2[0]-p0[0], p2[1]-p0[1], p2[2]-p0[2]};
        float nx = e1[1]*e2[2] - e1[2]*e2[1];
        float ny = e1[2]*e2[0] - e1[0]*e2[2];
        float nz = e1[0]*e2[1] - e1[1]*e2[0];
        float ss = nx*nx + ny*ny + nz*nz;
        s_plane[tid][0] = nx; s_plane[tid][1] = ny; s_plane[tid][2] = nz;
        s_plane[tid][3] = p0[0]; s_plane[tid][4] = p0[1]; s_plane[tid][5] = p0[2];
        s_plane[tid][6] = sqrtf(ss);       // |n|
        s_plane[tid][7] = ss + 1e-8f;      // n.n + eps
    }
    __syncthreads();

    // ---- step B (parallel split): 0-63 det geometry, 64-255 point prep ----
    if (tid < N_DET) {
        int d = tid;
        int cam = camidx[d];
        float K[9], CR[9], PR[9], ER[9], CT[3], PT[3], ET[3];
        #pragma unroll
        for (int i = 0; i < 3; i++) {
            #pragma unroll
            for (int j = 0; j < 3; j++) {
                K [i*3+j] = intr[cam*16 + i*4 + j];
                CR[i*3+j] = c2l [cam*16 + i*4 + j];
                PR[i*3+j] = iaug[cam*16 + i*4 + j];
                ER[i*3+j] = laug[i*4 + j];
            }
            CT[i] = c2l [cam*16 + i*4 + 3];
            PT[i] = iaug[cam*16 + i*4 + 3];
            ET[i] = laug[i*4 + 3];
        }
        float Kinv[9], CRinv[9], PRinv[9], ERinv[9];
        inv3(K, Kinv); inv3(CR, CRinv); inv3(PR, PRinv); inv3(ER, ERinv);

        float x1 = dbox[d*4+0], y1 = dbox[d*4+1], x2 = dbox[d*4+2], y2 = dbox[d*4+3];
        float lo[3] = {x1, y1, 2.0f}, hi[3] = {x2, y2, 60.0f};
        float whl[3] = {hi[0]-lo[0], hi[1]-lo[1], hi[2]-lo[2]};
        float ctr[3] = {(hi[0]+lo[0])*0.5f, (hi[1]+lo[1])*0.5f, (hi[2]+lo[2])*0.5f};

        float sum[3] = {0,0,0};
        float mn[3] = {1e30f, 1e30f, 1e30f}, mx[3] = {-1e30f, -1e30f, -1e30f};
        #pragma unroll
        for (int k = 0; k < 8; k++) {
            float ci[3], t0[3], t1[3], t2[3];
            #pragma unroll
            for (int c = 0; c < 3; c++) ci[c] = whl[c]*c_tmpl[k][c] + ctr[c] - PT[c];
            mv3(PRinv, ci, t0);
            t0[0] = t0[0]*t0[2]; t0[1] = t0[1]*t0[2];
            mv3(Kinv, t0, t1);
            mv3(CR, t1, t2);
            #pragma unroll
            for (int c = 0; c < 3; c++) t2[c] += CT[c];
            mv3(ER, t2, t0);
            #pragma unroll
            for (int c = 0; c < 3; c++) t0[c] += ET[c];
            float nrm = sqrtf(t0[0]*t0[0] + t0[1]*t0[1] + t0[2]*t0[2]);
            #pragma unroll
            for (int c = 0; c < 3; c++) {
                float dr = t0[c] / (nrm + 1e-8f);
                sum[c] += dr;
                mn[c] = fminf(mn[c], dr);
                mx[c] = fmaxf(mx[c], dr);
            }
        }
        #pragma unroll
        for (int c = 0; c < 3; c++) {
            s_mnmx[c][d]     = mn[c];
            s_mnmx[3 + c][d] = mx[c];
        }
        if (blockIdx.x == 0) {
            float cd[3] = {sum[0]/8.0f, sum[1]/8.0f, sum[2]/8.0f};
            float cn = sqrtf(cd[0]*cd[0] + cd[1]*cd[1] + cd[2]*cd[2]);
            #pragma unroll
            for (int c = 0; c < 3; c++) cd[c] = cd[c] / (cn + 1e-8f);
            float* G = g_det[d];
            for (int j = 0; j < 9; j++) { G[j] = K[j]; G[9+j] = CRinv[j]; G[18+j] = ERinv[j]; G[33+j] = PR[j]; }
            #pragma unroll
            for (int c = 0; c < 3; c++) {
                G[27+c] = CT[c]; G[30+c] = ET[c]; G[42+c] = PT[c];
                G[45+c] = cd[c];
                G[54+c] = anchors[labels[d]*3 + c];
            }
            G[57] = x1; G[58] = y1; G[59] = x2; G[60] = y2;
            G[61] = (x2 - x1) * (y2 - y1);
        }
    } else {
        // ---- point prep: 192 threads cover the chunk ----
        for (int j = tid - 64; j < CH; j += 192) {
            int i = start + j;
            float px = 2.0e9f, py = 0.0f, pz = 0.0f;
            unsigned nb0 = 0, nb1 = 0, nb2 = 0, ib = 0;
            if (i < N_PTS) {
                float4 pt = ((const float4*)points)[i];
                float x = pt.y, y = pt.z, z = pt.w;
                float pmag = sqrtf(x*x + y*y + z*z);
                float den = pmag + 1e-8f;
                py = y / den; pz = z / den;
                bool rok = (pmag >= 2.0f) && (pmag <= 60.0f);
                px = rok ? (x / den) : 2.0e9f;   // sentinel: direction test always fails

                #pragma unroll
                for (int m = 0; m < NUM_MAGS; m++) {
                    float mg = 2.0f + (float)m * (58.0f / 9.0f);
                    unsigned b = (fabsf(pmag - mg) < 5.8f) ? 1u : 0u;
                    if (m < 4)      nb0 |= b << (8 * m);
                    else if (m < 8) nb1 |= b << (8 * (m - 4));
                    else            nb2 |= b << (8 * (m - 8));
                }
                #pragma unroll
                for (int t = 0; t < NUM_TRIALS; t++) {
                    float nx = s_plane[t][0], ny = s_plane[t][1], nz = s_plane[t][2];
                    float dot = nx*(x - s_plane[t][3]) + ny*(y - s_plane[t][4]) + nz*(z - s_plane[t][5]);
                    float tt = dot / s_plane[t][7];
                    float dist = fabsf(tt) * s_plane[t][6];
                    ib |= ((dist < 0.69f) ? 1u : 0u) << (8 * t);
                }
            }
            s_p[j] = make_float4(px, py, pz, 0.0f);
            s_f[j] = make_uint4(nb0, nb1, nb2, ib);
        }
    }
    __syncthreads();

    // ---- phase 2: lane = det, 4 point-subgroups; warp reads are broadcast (conflict-free) ----
    int d = tid & 63;
    int g = tid >> 6;
    float mnx = s_mnmx[0][d], mny = s_mnmx[1][d], mnz = s_mnmx[2][d];
    float mxx = s_mnmx[3][d], mxy = s_mnmx[4][d], mxz = s_mnmx[5][d];

    unsigned msum = 0, a0 = 0, a1 = 0, a2 = 0, ai = 0;
    #pragma unroll 2
    for (int j = g; j < CH; j += 4) {
        float4 p = s_p[j];
        uint4  f = s_f[j];
        bool mk = (p.x >= mnx) & (p.x <= mxx) & (p.y >= mny) & (p.y <= mxy)
                & (p.z >= mnz) & (p.z <= mxz);
        if (mk) {
            msum += 1u;
            a0 += f.x; a1 += f.y; a2 += f.z; ai += f.w;
        }
    }
    s_acc[tid][0] = msum;
    s_acc[tid][1] = a0;
    s_acc[tid][2] = a1;
    s_acc[tid][3] = a2;
    s_acc[tid][4] = ai;
    __syncthreads();

    // ---- phase 3: 64 threads reduce 4 subgroups, unpack bytes, atomic add to global ----
    if (tid < N_DET) {
        int c[15];
        #pragma unroll
        for (int s = 0; s < 15; s++) c[s] = 0;
        #pragma unroll
        for (int r = 0; r < 4; r++) {
            const unsigned* w = s_acc[tid + 64 * r];
            c[0] += (int)w[0];
            unsigned w1 = w[1], w2 = w[2], w3 = w[3], w4 = w[4];
            #pragma unroll
            for (int b = 0; b < 4; b++) c[1 + b]  += (int)((w1 >> (8*b)) & 255u);
            #pragma unroll
            for (int b = 0; b < 4; b++) c[5 + b]  += (int)((w2 >> (8*b)) & 255u);
            #pragma unroll
            for (int b = 0; b < 2; b++) c[9 + b]  += (int)((w3 >> (8*b)) & 255u);
            #pragma unroll
            for (int b = 0; b < 4; b++) c[11 + b] += (int)((w4 >> (8*b)) & 255u);
        }
        #pragma unroll
        for (int s = 0; s < 15; s++) atomicAdd(&g_cnt[tid * 16 + s], c[s]);
    }
}

// ==================== K2: inline IoU + scoring + argmax + output (+ counter re-zero) ====================
__global__ void k_final(const float* __restrict__ det_scores, float* __restrict__ out) {
    int d = blockIdx.x;
    int t = threadIdx.x;
    __shared__ float sdns[NUM_MAGS];
    __shared__ float spln;
    __shared__ float ssc[128];
    __shared__ int   scnt[16];

    const float* G = g_det[d];

    if (t < 16) scnt[t] = g_cnt[d*16 + t];
    __syncthreads();
    if (t < 16) g_cnt[d*16 + t] = 0;    // leave clean for next launch
    if (t == 0) {
        float mxv = (float)scnt[1];
        for (int m = 1; m < NUM_MAGS; m++) mxv = fmaxf(mxv, (float)scnt[1 + m]);
        for (int m = 0; m < NUM_MAGS; m++) sdns[m] = (float)scnt[1 + m] / (mxv + 1e-6f);
        float msum = (float)scnt[0];
        float pln = -1e30f;
        for (int tt = 0; tt < NUM_TRIALS; tt++)
            pln = fmaxf(pln, ((float)scnt[11 + tt]) / (msum + 1e-6f));
        spln = pln;
    }

    float iou = 0.0f;
    if (t < 100) {
        float K[9], CRinv[9], ERinv[9], PR[9], CT[3], ET[3], PT[3], cd[3], sz[3];
        for (int j = 0; j < 9; j++) { K[j]=G[j]; CRinv[j]=G[9+j]; ERinv[j]=G[18+j]; PR[j]=G[33+j]; }
        #pragma unroll
        for (int c = 0; c < 3; c++) { CT[c]=G[27+c]; ET[c]=G[30+c]; PT[c]=G[42+c]; cd[c]=G[45+c]; sz[c]=G[54+c]; }
        float x1 = G[57], y1 = G[58], x2 = G[59], y2 = G[60], area_d = G[61];

        int m = t / 10, r = t % 10;
        float mag = 2.0f + (float)m * (58.0f / 9.0f);
        float ry  = (float)r * (3.14159265358979f / 9.0f);
        float cs = cosf(ry), sn = sinf(ry);
        float cen[3] = {cd[0]*mag, cd[1]*mag, cd[2]*mag};

        float umin = 1e30f, umax = -1e30f, vmin = 1e30f, vmax = -1e30f;
        #pragma unroll
        for (int k = 0; k < 8; k++) {
            float bx = sz[0]*c_tmpl[k][0], by = sz[1]*c_tmpl[k][1], bz = sz[2]*c_tmpl[k][2];
            float c3[3] = {cen[0] + bx*cs - by*sn, cen[1] + bx*sn + by*cs, cen[2] + bz};
            float t0[3], t1[3], t2[3];
            #pragma unroll
            for (int c = 0; c < 3; c++) t0[c] = c3[c] - ET[c];
            mv3(ERinv, t0, t1);
            #pragma unroll
            for (int c = 0; c < 3; c++) t1[c] -= CT[c];
            mv3(CRinv, t1, t2);
            mv3(K, t2, t0);
            float depth = fmaxf(t0[2], 0.001f);
            float qq[3] = {t0[0]/depth, t0[1]/depth, depth};
            mv3(PR, qq, t1);
            #pragma unroll
            for (int c = 0; c < 3; c++) t1[c] += PT[c];
            float u = fminf(fmaxf(t1[0], 0.0f), 1600.0f);
            float v = fminf(fmaxf(t1[1], 0.0f), 900.0f);
            umin = fminf(umin, u); umax = fmaxf(umax, u);
            vmin = fminf(vmin, v); vmax = fmaxf(vmax, v);
        }
        float ix1 = fmaxf(umin, x1), iy1 = fmaxf(vmin, y1);
        float ix2 = fminf(umax, x2), iy2 = fminf(vmax, y2);
        float inter = fmaxf(ix2 - ix1, 0.0f) * fmaxf(iy2 - iy1, 0.0f);
        float area_p = (umax - umin) * (vmax - vmin);
        iou = inter / (area_p + area_d - inter + 1e-6f);
    }
    __syncthreads();   // sdns/spln ready
    if (t < 100) {
        int m = t / 10;
        const float IOU_W = 0.91f, IOU_W1 = (float)(1.0 - 0.91);
        const float PLN_W = 0.92f, PLN_W1 = (float)(1.0 - 0.92);
        float base = IOU_W * iou + IOU_W1 * sdns[m];
        ssc[t] = PLN_W * base + PLN_W1 * spln;
    } else {
        ssc[t] = -1e30f;
    }
    __syncthreads();
    if (t == 0) {
        int best = 0; float bs = ssc[0];
        for (int i = 1; i < 100; i++) if (ssc[i] > bs) { bs = ssc[i]; best = i; }
        int m = best / 10, r = best % 10;
        float mag = 2.0f + (float)m * (58.0f / 9.0f);
        float* o = out + d*8;
        o[0] = G[45] * mag;
        o[1] = G[46] * mag;
        o[2] = G[47] * mag;
        o[3] = G[54]; o[4] = G[55]; o[5] = G[56];
        o[6] = (float)r * (3.14159265358979f / 9.0f);
        o[7] = bs * det_scores[d];
    }
}

// -------------------- launch --------------------
extern "C" void kernel_launch(void* const* d_in, const int* in_sizes, int n_in,
                              void* d_out, int out_size) {
    const float* points  = (const float*)d_in[0];
    const float* intr    = (const float*)d_in[1];
    const float* c2l     = (const float*)d_in[2];
    const float* iaug    = (const float*)d_in[3];
    const float* laug    = (const float*)d_in[4];
    const float* dbox    = (const float*)d_in[5];
    const float* dscores = (const float*)d_in[6];
    const float* anchors = (const float*)d_in[7];
    const int*   labels  = (const int*)d_in[8];
    const int*   camidx  = (const int*)d_in[9];
    float* out = (float*)d_out;

    k_main<<<NBLK, 256>>>(points, intr, c2l, iaug, laug, dbox, anchors, labels, camidx);
    k_final<<<N_DET, 128>>>(dscores, out);
}

// round 8
// speedup vs baseline: 1.5142x; 1.3761x over previous
#include <cuda_runtime.h>
#include <cuda_bf16.h>
#include <math.h>

#define N_PTS 250000
#define N_DET 64
#define NUM_MAGS 10
#define NUM_ROT 10
#define NUM_TRIALS 4
#define NBLK 296          // 2 blocks/SM x 148 SMs = exactly one wave
#define CH 845            // 296*845 = 250120 >= N_PTS

// -------------------- device scratch (no allocation allowed) --------------------
__device__ int   g_cnt[N_DET * 16];   // zero at load; k_final re-zeroes after use
__device__ float g_cs[N_DET][8];      // cd(3), sz(3) per det (block 0 writes)
__device__ float g_iou[N_DET * 100];  // written by k_main blocks 1..256

__constant__ float c_tmpl[8][3] = {
    { 0.5f,  0.5f, -0.5f}, { 0.5f, -0.5f, -0.5f}, {-0.5f, -0.5f, -0.5f}, {-0.5f,  0.5f, -0.5f},
    { 0.5f,  0.5f,  0.5f}, { 0.5f, -0.5f,  0.5f}, {-0.5f, -0.5f,  0.5f}, {-0.5f,  0.5f,  0.5f}};

__device__ __forceinline__ void inv3(const float* a, float* o) {
    float det = a[0]*(a[4]*a[8]-a[5]*a[7]) - a[1]*(a[3]*a[8]-a[5]*a[6]) + a[2]*(a[3]*a[7]-a[4]*a[6]);
    float id = 1.0f / det;
    o[0]=(a[4]*a[8]-a[5]*a[7])*id; o[1]=(a[2]*a[7]-a[1]*a[8])*id; o[2]=(a[1]*a[5]-a[2]*a[4])*id;
    o[3]=(a[5]*a[6]-a[3]*a[8])*id; o[4]=(a[0]*a[8]-a[2]*a[6])*id; o[5]=(a[2]*a[3]-a[0]*a[5])*id;
    o[6]=(a[3]*a[7]-a[4]*a[6])*id; o[7]=(a[1]*a[6]-a[0]*a[7])*id; o[8]=(a[0]*a[4]-a[1]*a[3])*id;
}

__device__ __forceinline__ void mv3(const float* M, const float* v, float* o) {
    o[0] = M[0]*v[0] + M[1]*v[1] + M[2]*v[2];
    o[1] = M[3]*v[0] + M[4]*v[1] + M[5]*v[2];
    o[2] = M[6]*v[0] + M[7]*v[1] + M[8]*v[2];
}

// s_geo layout (56 floats): 0 K9, 9 CRinv9, 18 ERinv9, 27 PR9, 36 CT3, 39 ET3,
// 42 PT3, 45 cd3, 48 sz3, 51 box4, 55 area_d

// ==================== K1: fused setup + prep + IoU + (det,point) accumulation ====================
__global__ void __launch_bounds__(256, 2) k_main(
        const float* __restrict__ points,
        const float* __restrict__ intr, const float* __restrict__ c2l,
        const float* __restrict__ iaug, const float* __restrict__ laug,
        const float* __restrict__ dbox, const float* __restrict__ anchors,
        const int* __restrict__ labels, const int* __restrict__ camidx) {
    __shared__ float    s_plane[NUM_TRIALS][8];
    __shared__ float    s_mnmx[6][N_DET];
    __shared__ float    s_geo[56];
    __shared__ float4   s_p[CH];
    __shared__ uint4    s_f[CH];
    __shared__ unsigned s_acc[256][6];   // 4 used + pad

    const int tid = threadIdx.x;
    const int start = blockIdx.x * CH;
    const int bm1 = (int)blockIdx.x - 1;
    const int dd_blk = (bm1 >= 0 && bm1 < 256) ? (bm1 >> 2) : -1;  // det this block scores

    // ---- step A: geometry threads issue their LDGs early; planes on threads 224-227 ----
    float K[9], CR[9], PR[9], ER[9], CT[3], PT[3], ET[3], bx4[4], anc[3];
    if (tid < N_DET) {
        int cam = camidx[tid];
        int lbl = labels[tid];
        #pragma unroll
        for (int i = 0; i < 3; i++) {
            #pragma unroll
            for (int j = 0; j < 3; j++) {
                K [i*3+j] = intr[cam*16 + i*4 + j];
                CR[i*3+j] = c2l [cam*16 + i*4 + j];
                PR[i*3+j] = iaug[cam*16 + i*4 + j];
                ER[i*3+j] = laug[i*4 + j];
            }
            CT[i] = c2l [cam*16 + i*4 + 3];
            PT[i] = iaug[cam*16 + i*4 + 3];
            ET[i] = laug[i*4 + 3];
        }
        #pragma unroll
        for (int c = 0; c < 4; c++) bx4[c] = dbox[tid*4 + c];
        #pragma unroll
        for (int c = 0; c < 3; c++) anc[c] = anchors[lbl*3 + c];
    } else if (tid >= 224 && tid < 224 + NUM_TRIALS) {
        int t = tid - 224;
        const int step = N_PTS / 3;  // 83333
        float p0[3], p1[3], p2[3];
        #pragma unroll
        for (int c = 0; c < 3; c++) {
            p0[c] = points[(t)            * 4 + 1 + c];
            p1[c] = points[(t + step)     * 4 + 1 + c];
            p2[c] = points[(t + 2 * step) * 4 + 1 + c];
        }
        float e1[3] = {p1[0]-p0[0], p1[1]-p0[1], p1[2]-p0[2]};
        float e2[3] = {p2[0]-p0[0], p2[1]-p0[1], p2[2]-p0[2]};
        float nx = e1[1]*e2[2] - e1[2]*e2[1];
        float ny = e1[2]*e2[0] - e1[0]*e2[2];
        float nz = e1[0]*e2[1] - e1[1]*e2[0];
        float ss = nx*nx + ny*ny + nz*nz;
        s_plane[t][0] = nx; s_plane[t][1] = ny; s_plane[t][2] = nz;
        s_plane[t][3] = p0[0]; s_plane[t][4] = p0[1]; s_plane[t][5] = p0[2];
        s_plane[t][6] = sqrtf(ss);
        s_plane[t][7] = ss + 1e-8f;
    }
    __syncthreads();

    // ---- step B: 0-63 geometry compute; 64-255 point prep ----
    if (tid < N_DET) {
        int d = tid;
        float Kinv[9], CRinv[9], PRinv[9], ERinv[9];
        inv3(K, Kinv); inv3(CR, CRinv); inv3(PR, PRinv); inv3(ER, ERinv);

        float x1 = bx4[0], y1 = bx4[1], x2 = bx4[2], y2 = bx4[3];
        float lo[3] = {x1, y1, 2.0f}, hi[3] = {x2, y2, 60.0f};
        float whl[3] = {hi[0]-lo[0], hi[1]-lo[1], hi[2]-lo[2]};
        float ctr[3] = {(hi[0]+lo[0])*0.5f, (hi[1]+lo[1])*0.5f, (hi[2]+lo[2])*0.5f};

        float sum[3] = {0,0,0};
        float mn[3] = {1e30f, 1e30f, 1e30f}, mx[3] = {-1e30f, -1e30f, -1e30f};
        #pragma unroll
        for (int k = 0; k < 8; k++) {
            float ci[3], t0[3], t1[3], t2[3];
            #pragma unroll
            for (int c = 0; c < 3; c++) ci[c] = whl[c]*c_tmpl[k][c] + ctr[c] - PT[c];
            mv3(PRinv, ci, t0);
            t0[0] = t0[0]*t0[2]; t0[1] = t0[1]*t0[2];
            mv3(Kinv, t0, t1);
            mv3(CR, t1, t2);
            #pragma unroll
            for (int c = 0; c < 3; c++) t2[c] += CT[c];
            mv3(ER, t2, t0);
            #pragma unroll
            for (int c = 0; c < 3; c++) t0[c] += ET[c];
            float nrm = sqrtf(t0[0]*t0[0] + t0[1]*t0[1] + t0[2]*t0[2]);
            #pragma unroll
            for (int c = 0; c < 3; c++) {
                float dr = t0[c] / (nrm + 1e-8f);
                sum[c] += dr;
                mn[c] = fminf(mn[c], dr);
                mx[c] = fmaxf(mx[c], dr);
            }
        }
        #pragma unroll
        for (int c = 0; c < 3; c++) {
            s_mnmx[c][d]     = mn[c];
            s_mnmx[3 + c][d] = mx[c];
        }
        float cd[3] = {sum[0]/8.0f, sum[1]/8.0f, sum[2]/8.0f};
        float cn = sqrtf(cd[0]*cd[0] + cd[1]*cd[1] + cd[2]*cd[2]);
        #pragma unroll
        for (int c = 0; c < 3; c++) cd[c] = cd[c] / (cn + 1e-8f);

        if (d == dd_blk) {   // this block will score det d: stash geometry in shared
            #pragma unroll
            for (int j = 0; j < 9; j++) {
                s_geo[j] = K[j]; s_geo[9+j] = CRinv[j]; s_geo[18+j] = ERinv[j]; s_geo[27+j] = PR[j];
            }
            #pragma unroll
            for (int c = 0; c < 3; c++) {
                s_geo[36+c] = CT[c]; s_geo[39+c] = ET[c]; s_geo[42+c] = PT[c];
                s_geo[45+c] = cd[c]; s_geo[48+c] = anc[c];
            }
            s_geo[51] = x1; s_geo[52] = y1; s_geo[53] = x2; s_geo[54] = y2;
            s_geo[55] = (x2 - x1) * (y2 - y1);
        }
        if (blockIdx.x == 0) {
            #pragma unroll
            for (int c = 0; c < 3; c++) { g_cs[d][c] = cd[c]; g_cs[d][3+c] = anc[c]; }
        }
    } else {
        // ---- point prep: 192 threads cover the chunk ----
        for (int j = tid - 64; j < CH; j += 192) {
            int i = start + j;
            float px = 2.0e9f, py = 0.0f, pz = 0.0f;
            unsigned nb0 = 0, nb1 = 0, nb2 = 0x10000u, ib = 0;  // byte2 of w3 = msum constant 1
            if (i < N_PTS) {
                float4 pt = ((const float4*)points)[i];
                float x = pt.y, y = pt.z, z = pt.w;
                float pmag = sqrtf(x*x + y*y + z*z);
                float den = pmag + 1e-8f;
                py = y / den; pz = z / den;
                bool rok = (pmag >= 2.0f) && (pmag <= 60.0f);
                px = rok ? (x / den) : 2.0e9f;   // sentinel: direction test always fails

                #pragma unroll
                for (int m = 0; m < NUM_MAGS; m++) {
                    float mg = 2.0f + (float)m * (58.0f / 9.0f);
                    unsigned b = (fabsf(pmag - mg) < 5.8f) ? 1u : 0u;
                    if (m < 4)      nb0 |= b << (8 * m);
                    else if (m < 8) nb1 |= b << (8 * (m - 4));
                    else            nb2 |= b << (8 * (m - 8));
                }
                #pragma unroll
                for (int t = 0; t < NUM_TRIALS; t++) {
                    float nx = s_plane[t][0], ny = s_plane[t][1], nz = s_plane[t][2];
                    float dot = nx*(x - s_plane[t][3]) + ny*(y - s_plane[t][4]) + nz*(z - s_plane[t][5]);
                    float tt = dot / s_plane[t][7];
                    float dist = fabsf(tt) * s_plane[t][6];
                    ib |= ((dist < 0.69f) ? 1u : 0u) << (8 * t);
                }
            }
            s_p[j] = make_float4(px, py, pz, 0.0f);
            s_f[j] = make_uint4(nb0, nb1, nb2, ib);
        }
    }
    __syncthreads();

    // ---- IoU: blocks 1..256 score 25 combos of det dd_blk (threads 128-152), then join phase 2 ----
    if (dd_blk >= 0 && tid >= 128 && tid < 128 + 25) {
        int combo = (bm1 & 3) * 25 + (tid - 128);   // 0..99
        int m = combo / 10, r = combo % 10;
        float mag = 2.0f + (float)m * (58.0f / 9.0f);
        float ry  = (float)r * (3.14159265358979f / 9.0f);
        float cs = cosf(ry), sn = sinf(ry);
        float cen[3] = {s_geo[45]*mag, s_geo[46]*mag, s_geo[47]*mag};
        float umin = 1e30f, umax = -1e30f, vmin = 1e30f, vmax = -1e30f;
        #pragma unroll
        for (int k = 0; k < 8; k++) {
            float bx = s_geo[48]*c_tmpl[k][0], by = s_geo[49]*c_tmpl[k][1], bz = s_geo[50]*c_tmpl[k][2];
            float c3[3] = {cen[0] + bx*cs - by*sn, cen[1] + bx*sn + by*cs, cen[2] + bz};
            float t0[3], t1[3], t2[3];
            #pragma unroll
            for (int c = 0; c < 3; c++) t0[c] = c3[c] - s_geo[39+c];
            mv3(&s_geo[18], t0, t1);                       // ERinv
            #pragma unroll
            for (int c = 0; c < 3; c++) t1[c] -= s_geo[36+c];
            mv3(&s_geo[9], t1, t2);                        // CRinv
            mv3(&s_geo[0], t2, t0);                        // K
            float depth = fmaxf(t0[2], 0.001f);
            float qq[3] = {t0[0]/depth, t0[1]/depth, depth};
            mv3(&s_geo[27], qq, t1);                       // PR
            #pragma unroll
            for (int c = 0; c < 3; c++) t1[c] += s_geo[42+c];
            float u = fminf(fmaxf(t1[0], 0.0f), 1600.0f);
            float v = fminf(fmaxf(t1[1], 0.0f), 900.0f);
            umin = fminf(umin, u); umax = fmaxf(umax, u);
            vmin = fminf(vmin, v); vmax = fmaxf(vmax, v);
        }
        float ix1 = fmaxf(umin, s_geo[51]), iy1 = fmaxf(vmin, s_geo[52]);
        float ix2 = fminf(umax, s_geo[53]), iy2 = fminf(vmax, s_geo[54]);
        float inter = fmaxf(ix2 - ix1, 0.0f) * fmaxf(iy2 - iy1, 0.0f);
        float area_p = (umax - umin) * (vmax - vmin);
        g_iou[dd_blk*100 + combo] = inter / (area_p + s_geo[55] - inter + 1e-6f);
    }

    // ---- phase 2: lane = det, 4 point-subgroups; warp reads broadcast/stride-1 ----
    int d = tid & 63;
    int g = tid >> 6;
    float mnx = s_mnmx[0][d], mny = s_mnmx[1][d], mnz = s_mnmx[2][d];
    float mxx = s_mnmx[3][d], mxy = s_mnmx[4][d], mxz = s_mnmx[5][d];

    unsigned a0 = 0, a1 = 0, a2 = 0, ai = 0;
    #pragma unroll 4
    for (int j = g; j < CH; j += 4) {
        float4 p = s_p[j];
        uint4  f = s_f[j];
        bool mk = (p.x >= mnx) & (p.x <= mxx) & (p.y >= mny) & (p.y <= mxy)
                & (p.z >= mnz) & (p.z <= mxz);
        if (mk) {
            a0 += f.x; a1 += f.y; a2 += f.z; ai += f.w;   // f.z byte2 carries msum
        }
    }
    s_acc[tid][0] = a0;
    s_acc[tid][1] = a1;
    s_acc[tid][2] = a2;
    s_acc[tid][3] = ai;
    __syncthreads();

    // ---- phase 3: 64 threads reduce 4 subgroups, unpack bytes, atomic add to global ----
    if (tid < N_DET) {
        int c[15];
        #pragma unroll
        for (int s = 0; s < 15; s++) c[s] = 0;
        #pragma unroll
        for (int r = 0; r < 4; r++) {
            const unsigned* w = s_acc[tid + 64 * r];
            unsigned w0 = w[0], w1 = w[1], w2 = w[2], w3 = w[3];
            #pragma unroll
            for (int b = 0; b < 4; b++) c[1 + b]  += (int)((w0 >> (8*b)) & 255u);  // bins 0-3
            #pragma unroll
            for (int b = 0; b < 4; b++) c[5 + b]  += (int)((w1 >> (8*b)) & 255u);  // bins 4-7
            c[9]  += (int)(w2 & 255u);            // bin 8
            c[10] += (int)((w2 >> 8) & 255u);     // bin 9
            c[0]  += (int)((w2 >> 16) & 255u);    // msum
            #pragma unroll
            for (int b = 0; b < 4; b++) c[11 + b] += (int)((w3 >> (8*b)) & 255u);  // inliers
        }
        #pragma unroll
        for (int s = 0; s < 15; s++) atomicAdd(&g_cnt[tid * 16 + s], c[s]);
    }
}

// ==================== K2: scoring + parallel argmax + output (+ counter re-zero) ====================
__global__ void __launch_bounds__(128) k_final(const float* __restrict__ det_scores,
                                               float* __restrict__ out) {
    int d = blockIdx.x;
    int t = threadIdx.x;
    __shared__ float sdns[NUM_MAGS];
    __shared__ float spln;
    __shared__ float ssc[128];
    __shared__ int   scnt[16];

    float iou = (t < 100) ? g_iou[d*100 + t] : 0.0f;   // issue LDG early
    if (t < 16) scnt[t] = g_cnt[d*16 + t];
    __syncthreads();
    if (t < 16) g_cnt[d*16 + t] = 0;    // leave clean for next launch
    if (t == 0) {
        float mxv = (float)scnt[1];
        for (int m = 1; m < NUM_MAGS; m++) mxv = fmaxf(mxv, (float)scnt[1 + m]);
        for (int m = 0; m < NUM_MAGS; m++) sdns[m] = (float)scnt[1 + m] / (mxv + 1e-6f);
        float msum = (float)scnt[0];
        float pln = -1e30f;
        for (int tt = 0; tt < NUM_TRIALS; tt++)
            pln = fmaxf(pln, ((float)scnt[11 + tt]) / (msum + 1e-6f));
        spln = pln;
    }
    __syncthreads();

    if (t < 100) {
        const float IOU_W = 0.91f, IOU_W1 = (float)(1.0 - 0.91);
        const float PLN_W = 0.92f, PLN_W1 = (float)(1.0 - 0.92);
        float base = IOU_W * iou + IOU_W1 * sdns[t / 10];
        ssc[t] = PLN_W * base + PLN_W1 * spln;
    } else {
        ssc[t] = -1e30f;
    }
    __syncthreads();

    // parallel argmax (warp 0): key = (monotone(score), 127-idx) -> first max index
    if (t < 32) {
        unsigned long long best = 0ULL;
        #pragma unroll
        for (int k = 0; k < 4; k++) {
            int idx = t + 32*k;
            unsigned b = __float_as_uint(ssc[idx]);
            unsigned mb = b ^ ((b >> 31) ? 0xFFFFFFFFu : 0x80000000u);  // monotone map
            unsigned long long key = ((unsigned long long)mb << 32) | (unsigned)(127 - idx);
            best = (key > best) ? key : best;
        }
        #pragma unroll
        for (int s = 16; s >= 1; s >>= 1) {
            unsigned long long o = __shfl_xor_sync(0xFFFFFFFFu, best, s);
            best = (o > best) ? o : best;
        }
        if (t == 0) {
            int idx = 127 - (int)(best & 0x7Fu);
            float bs = ssc[idx];
            int m = idx / 10, r = idx % 10;
            float mag = 2.0f + (float)m * (58.0f / 9.0f);
            float* o = out + d*8;
            o[0] = g_cs[d][0] * mag;
            o[1] = g_cs[d][1] * mag;
            o[2] = g_cs[d][2] * mag;
            o[3] = g_cs[d][3]; o[4] = g_cs[d][4]; o[5] = g_cs[d][5];
            o[6] = (float)r * (3.14159265358979f / 9.0f);
            o[7] = bs * det_scores[d];
        }
    }
}

// -------------------- launch --------------------
extern "C" void kernel_launch(void* const* d_in, const int* in_sizes, int n_in,
                              void* d_out, int out_size) {
    const float* points  = (const float*)d_in[0];
    const float* intr    = (const float*)d_in[1];
    const float* c2l     = (const float*)d_in[2];
    const float* iaug    = (const float*)d_in[3];
    const float* laug    = (const float*)d_in[4];
    const float* dbox    = (const float*)d_in[5];
    const float* dscores = (const float*)d_in[6];
    const float* anchors = (const float*)d_in[7];
    const int*   labels  = (const int*)d_in[8];
    const int*   camidx  = (const int*)d_in[9];
    float* out = (float*)d_out;

    k_main<<<NBLK, 256>>>(points, intr, c2l, iaug, laug, dbox, anchors, labels, camidx);
    k_final<<<N_DET, 128>>>(dscores, out);
}